// round 16
// baseline (speedup 1.0000x reference)
#include <cuda_runtime.h>
#include <cuda_bf16.h>
#include <cuda_fp16.h>
#include <cstdint>
#include <math.h>

// ---------------- problem constants ----------------
#define CDIM 256
#define HEADS 8
#define DH 32
#define BATCH 8
#define QPER 128
#define KVPER 1024
#define NQ (BATCH*QPER)      // 1024
#define NKV (BATCH*KVPER)    // 8192
#define RMS_EPS 1.1920928955078125e-07f
#define ATTN_SCALE 0.17677669529663687f  // 1/sqrt(32)
#define NSPLIT 4             // cross-attn key splits

// ---------------- scratch (device globals; no cudaMalloc allowed) ----------
__device__ __align__(16) __half g_Kc16[NKV*CDIM];
__device__ __align__(16) __half g_Vc16[NKV*CDIM];
__device__ __align__(16) __half g_mh16[NQ*CDIM];
__device__ __align__(16) __half g_mk16[NQ*CDIM];       // mk with w_norm_kv folded
__device__ __align__(16) __half g_z16[NQ*KVPER];       // mask logits [q][kv_local]
__device__ __align__(16) __half g_Qc16[NQ*CDIM];
__device__ __align__(16) __half g_attn16[NQ*CDIM];
__device__ __align__(16) float  g_q1 [NQ*CDIM];
__device__ __align__(16) __half g_q116[NQ*CDIM];
__device__ __align__(16) float  g_q2 [NQ*CDIM];
__device__ __align__(16) __half g_q216[NQ*CDIM];
__device__ __align__(16) __half g_Qs16[NQ*CDIM];
__device__ __align__(16) __half g_KVs16[NQ*2*CDIM];
__device__ __align__(16) __half g_hid16[NQ*4*CDIM];
__device__ __align__(16) __half g_po16[NSPLIT*64*QPER*DH];
__device__ __align__(16) float  g_pm [NSPLIT*64*QPER];
__device__ __align__(16) float  g_pl [NSPLIT*64*QPER];
// f16 weights (folded where applicable) and f16 inputs
__device__ __align__(16) __half g_wqc16 [CDIM*CDIM];
__device__ __align__(16) __half g_wkc16 [CDIM*CDIM];
__device__ __align__(16) __half g_wvc16 [CDIM*CDIM];
__device__ __align__(16) __half g_wqs16 [CDIM*CDIM];
__device__ __align__(16) __half g_wkvs16[2*CDIM*CDIM];
__device__ __align__(16) __half g_w116  [4*CDIM*CDIM];
__device__ __align__(16) __half g_w1m16 [CDIM*CDIM];
__device__ __align__(16) __half g_w2m16 [CDIM*CDIM];
__device__ __align__(16) __half g_woc16 [CDIM*CDIM];
__device__ __align__(16) __half g_wos16 [CDIM*CDIM];
__device__ __align__(16) __half g_w216  [CDIM*4*CDIM];
__device__ __align__(16) __half g_q16   [NQ*CDIM];
__device__ __align__(16) __half g_kv16  [NKV*CDIM];
// per-row inv-rms scales / sum-of-squares
__device__ float g_skv [NKV];
__device__ float g_sq  [NQ];
__device__ float g_ssq1[NQ];
__device__ float g_ssq2[NQ];

// ---------------- fast exp / log (FMA-pipe polys, no MUFU) -----------------
__device__ __forceinline__ float fexp(float x) {
    float y = x * 1.44269504088896340736f;
    y = fminf(fmaxf(y, -126.0f), 126.0f);
    float r = rintf(y);
    float f = y - r;
    float p = 1.3333558146428443e-3f;
    p = fmaf(p, f, 9.6181291076284772e-3f);
    p = fmaf(p, f, 5.5504108664821580e-2f);
    p = fmaf(p, f, 2.4022650695910072e-1f);
    p = fmaf(p, f, 6.9314718055994531e-1f);
    p = fmaf(p, f, 1.0f);
    float s = __int_as_float(((int)r + 127) << 23);
    return p * s;
}

__device__ __forceinline__ float flog(float x) {
    int ix = __float_as_int(x);
    int e = (ix - 0x3f3504f3) >> 23;
    float m = __int_as_float(ix - (e << 23));
    float f = m - 1.0f;
    float z = f * f;
    float p = 7.0376836292e-2f;
    p = fmaf(p, f, -1.1514610310e-1f);
    p = fmaf(p, f,  1.1676998740e-1f);
    p = fmaf(p, f, -1.2420140846e-1f);
    p = fmaf(p, f,  1.4249322787e-1f);
    p = fmaf(p, f, -1.6668057665e-1f);
    p = fmaf(p, f,  2.0000714765e-1f);
    p = fmaf(p, f, -2.4999993993e-1f);
    p = fmaf(p, f,  3.3333331174e-1f);
    float y = f * z * p;
    y = fmaf(-0.5f, z, y);
    return fmaf((float)e, 0.693147180559945f, f + y);
}

// ---------------- ldmatrix helpers ------------------------------------------
#define LDSM_X4(r0, r1, r2, r3, addr) \
    asm volatile("ldmatrix.sync.aligned.m8n8.x4.shared.b16 {%0,%1,%2,%3}, [%4];" \
        : "=r"(r0), "=r"(r1), "=r"(r2), "=r"(r3) : "r"(addr))
#define LDSM_X2(r0, r1, addr) \
    asm volatile("ldmatrix.sync.aligned.m8n8.x2.shared.b16 {%0,%1}, [%2];" \
        : "=r"(r0), "=r"(r1) : "r"(addr))

__device__ __forceinline__ unsigned smem_u32(const void* p) {
    return (unsigned)__cvta_generic_to_shared(p);
}

// ---------------- prep (vectorized): weights cvt + q/kv cvt + row rms + zero
#define PREP_A 1152
#define PREP_B 2304
#define PREP_C 8
__global__ __launch_bounds__(256)
void prep(const float* __restrict__ wq_c, const float* __restrict__ wk_c,
          const float* __restrict__ wv_c, const float* __restrict__ wq_s,
          const float* __restrict__ wkv_s, const float* __restrict__ w1,
          const float* __restrict__ w1m, const float* __restrict__ w2m,
          const float* __restrict__ woc, const float* __restrict__ wos,
          const float* __restrict__ w2,
          const float* __restrict__ n1, const float* __restrict__ nkv,
          const float* __restrict__ n2, const float* __restrict__ n3,
          const float* __restrict__ kv, const float* __restrict__ q)
{
    int bid = blockIdx.x;
    int tid = threadIdx.x;
    if (bid < PREP_A) {
        int i = bid*1024 + tid*4;
        const float* src; __half* dst; const float* nrm; int off;
        if      (i <   65536) { src=wq_c;  dst=g_wqc16;  nrm=n1;     off=0; }
        else if (i <  131072) { src=wk_c;  dst=g_wkc16;  nrm=nkv;    off=65536; }
        else if (i <  196608) { src=wv_c;  dst=g_wvc16;  nrm=nkv;    off=131072; }
        else if (i <  262144) { src=wq_s;  dst=g_wqs16;  nrm=n2;     off=196608; }
        else if (i <  393216) { src=wkv_s; dst=g_wkvs16; nrm=n2;     off=262144; }
        else if (i <  655360) { src=w1;    dst=g_w116;   nrm=n3;     off=393216; }
        else if (i <  720896) { src=w1m;   dst=g_w1m16;  nrm=nullptr;off=655360; }
        else if (i <  786432) { src=w2m;   dst=g_w2m16;  nrm=nullptr;off=720896; }
        else if (i <  851968) { src=woc;   dst=g_woc16;  nrm=nullptr;off=786432; }
        else if (i <  917504) { src=wos;   dst=g_wos16;  nrm=nullptr;off=851968; }
        else                  { src=w2;    dst=g_w216;   nrm=nullptr;off=917504; }
        int j = i - off;
        float4 v = *reinterpret_cast<const float4*>(&src[j]);
        if (nrm) {
            int k = j & 255;
            v.x *= nrm[k]; v.y *= nrm[k+1]; v.z *= nrm[k+2]; v.w *= nrm[k+3];
        }
        __half2 h0 = __floats2half2_rn(v.x, v.y);
        __half2 h1 = __floats2half2_rn(v.z, v.w);
        *reinterpret_cast<__half2*>(&dst[j])   = h0;
        *reinterpret_cast<__half2*>(&dst[j+2]) = h1;
    } else if (bid < PREP_A + PREP_B) {
        int rbase = (bid - PREP_A) * 4;
        int rloc = tid >> 6;
        int col = (tid & 63) * 4;
        int r = rbase + rloc;
        const float* src; __half* dst;
        if (r < NQ) { src = q + (size_t)r*CDIM; dst = g_q16 + (size_t)r*CDIM; }
        else { int rr = r - NQ; src = kv + (size_t)rr*CDIM; dst = g_kv16 + (size_t)rr*CDIM; }
        float4 v = *reinterpret_cast<const float4*>(&src[col]);
        __half2 h0 = __floats2half2_rn(v.x, v.y);
        __half2 h1 = __floats2half2_rn(v.z, v.w);
        *reinterpret_cast<__half2*>(&dst[col])   = h0;
        *reinterpret_cast<__half2*>(&dst[col+2]) = h1;
        float ss = fmaf(v.x, v.x, fmaf(v.y, v.y, fmaf(v.z, v.z, v.w*v.w)));
        #pragma unroll
        for (int o = 16; o > 0; o >>= 1) ss += __shfl_xor_sync(0xffffffffu, ss, o);
        __shared__ float red[8];
        if ((tid & 31) == 0) red[tid >> 5] = ss;
        __syncthreads();
        if (tid < 4) {
            float s = red[2*tid] + red[2*tid+1];
            float inv = rsqrtf(s*(1.0f/CDIM) + RMS_EPS);
            int rw = rbase + tid;
            if (rw < NQ) g_sq[rw] = inv;
            else         g_skv[rw - NQ] = inv;
        }
    } else {
        int i = (bid - PREP_A - PREP_B)*256 + tid;
        if (i < NQ) g_ssq1[i] = 0.f;
        else        g_ssq2[i - NQ] = 0.f;
    }
}

// ---------------- grouped f16 GEMM: BM=64, BN=128, BK=64, 256 thr ----------
// 8 warps (2x4), warp tile 32x32. Double-buffered cp.async.
// C = epi( scale * diag(rowscale) * A @ B^T ), f16 inputs, fp32 accumulate.
#define BKG 64
#define PADH 72
#define MAXJOBS 11

struct Job {
    const __half *A, *B;
    const float *bias, *res, *rowS, *rowSS, *colS;
    float *C; __half *C16; float *ssOut;
    int N, K, nblocks, nb_total, mode;
    float scale;
};
struct JobPack { Job jobs[MAXJOBS]; int njobs; };

__device__ __forceinline__ void cp_async16(void* smem, const void* gmem) {
    unsigned s = (unsigned)__cvta_generic_to_shared(smem);
    asm volatile("cp.async.cg.shared.global [%0], [%1], 16;\n" :: "r"(s), "l"(gmem));
}
#define CP_COMMIT() asm volatile("cp.async.commit_group;\n" ::: "memory")
#define CP_WAIT1()  asm volatile("cp.async.wait_group 1;\n" ::: "memory")

#define MMA_F16(acc, a, b0, b1) \
    asm volatile("mma.sync.aligned.m16n8k16.row.col.f32.f16.f16.f32 " \
        "{%0,%1,%2,%3}, {%4,%5,%6,%7}, {%8,%9}, {%0,%1,%2,%3};" \
        : "+f"(acc[0]), "+f"(acc[1]), "+f"(acc[2]), "+f"(acc[3]) \
        : "r"(a[0]), "r"(a[1]), "r"(a[2]), "r"(a[3]), "r"(b0), "r"(b1))

__global__ __launch_bounds__(256)
void gemm_grouped(JobPack P)
{
    int bid = blockIdx.x;
    int j = 0;
    #pragma unroll 1
    while (j < P.njobs - 1 && bid >= P.jobs[j].nb_total) { bid -= P.jobs[j].nb_total; ++j; }
    const Job jb = P.jobs[j];

    int xb = bid % jb.nblocks, yb = bid / jb.nblocks;
    int m0 = yb * 64, n0 = xb * 128;
    const __half* A = jb.A;
    const __half* B = jb.B;
    int K = jb.K;

    __shared__ __align__(16) __half As[2][64][PADH];
    __shared__ __align__(16) __half Bs[2][128][PADH];

    int tid = threadIdx.x;
    int warp = tid >> 5, lane = tid & 31;
    int wm = (warp >> 2) * 32;        // 2 m-warps
    int wn = (warp & 3) * 32;         // 4 n-warps
    int g = lane >> 2, t = lane & 3;

    // ldmatrix address components
    int arow = lane & 15, acol8 = (lane >> 4) << 3;        // A x4
    int brow = lane & 7,  bcol8 = ((lane >> 3) & 1) << 3;  // B x2

    float acc[2][4][4];
    #pragma unroll
    for (int i = 0; i < 2; ++i)
        #pragma unroll
        for (int jj = 0; jj < 4; ++jj)
            #pragma unroll
            for (int k = 0; k < 4; ++k) acc[i][jj][k] = 0.f;

    // stage = BK=64 halfs/row: A 64 rows x 8 chunks = 512, B 128x8 = 1024 -> 6/thread
    auto load_stage = [&](int st, int kk) {
        #pragma unroll
        for (int i = 0; i < 6; ++i) {
            int ch = tid + i*256;
            if (ch < 512) {
                int r = ch >> 3, c = (ch & 7) << 3;
                cp_async16(&As[st][r][c], &A[(size_t)(m0 + r)*K + kk + c]);
            } else {
                int ch2 = ch - 512;
                int r = ch2 >> 3, c = (ch2 & 7) << 3;
                cp_async16(&Bs[st][r][c], &B[(size_t)(n0 + r)*K + kk + c]);
            }
        }
    };

    int NIT = K >> 6;
    load_stage(0, 0);
    CP_COMMIT();
    if (NIT > 1) load_stage(1, BKG);
    CP_COMMIT();

    for (int it = 0; it < NIT; ++it) {
        CP_WAIT1();
        __syncthreads();
        int st = it & 1;
        #pragma unroll
        for (int ks = 0; ks < 4; ++ks) {      // four k16 slices
            int kb = ks * 16;
            unsigned af[2][4], bf[4][2];
            #pragma unroll
            for (int mt = 0; mt < 2; ++mt) {
                unsigned addr = smem_u32(&As[st][wm + mt*16 + arow][kb + acol8]);
                LDSM_X4(af[mt][0], af[mt][1], af[mt][2], af[mt][3], addr);
            }
            #pragma unroll
            for (int nt = 0; nt < 4; ++nt) {
                unsigned addr = smem_u32(&Bs[st][wn + nt*8 + brow][kb + bcol8]);
                LDSM_X2(bf[nt][0], bf[nt][1], addr);
            }
            #pragma unroll
            for (int mt = 0; mt < 2; ++mt)
                #pragma unroll
                for (int nt = 0; nt < 4; ++nt)
                    MMA_F16(acc[mt][nt], af[mt], bf[nt][0], bf[nt][1]);
        }
        __syncthreads();
        if (it + 2 < NIT) load_stage(st, (it+2)*BKG);
        CP_COMMIT();
    }

    // epilogue
    int N = jb.N;
    float ssacc[2][2] = {{0.f,0.f},{0.f,0.f}};
    #pragma unroll
    for (int mt = 0; mt < 2; ++mt) {
        #pragma unroll
        for (int nt = 0; nt < 4; ++nt) {
            float* cc = acc[mt][nt];
            int row = m0 + wm + mt*16 + g;
            int col = n0 + wn + nt*8 + 2*t;
            #pragma unroll
            for (int hh = 0; hh < 2; ++hh) {
                int rr = row + hh*8;
                float rs = 1.0f;
                if (jb.rowSS)     rs = rsqrtf(jb.rowSS[rr]*(1.0f/CDIM) + RMS_EPS);
                else if (jb.rowS) rs = jb.rowS[rr];
                float v0 = cc[hh*2+0] * jb.scale * rs;
                float v1 = cc[hh*2+1] * jb.scale * rs;
                if (jb.mode == 1) {
                    v0 += jb.bias[col];   v1 += jb.bias[col+1];
                    v0 = 0.5f * v0 * (1.0f + erff(v0 * 0.70710678118654752f));
                    v1 = 0.5f * v1 * (1.0f + erff(v1 * 0.70710678118654752f));
                } else if (jb.mode == 2) {
                    if (jb.colS) { v0 *= jb.colS[col]; v1 *= jb.colS[col+1]; }
                    float u0 = 1.0f + fexp(-v0);
                    float u1 = 1.0f + fexp(-v1);
                    float w0 = 1e-6f*u0, w1 = 1e-6f*u1;
                    float lp0 = w0*fmaf(w0, fmaf(w0, 0.333333333f, -0.5f), 1.0f);
                    float lp1 = w1*fmaf(w1, fmaf(w1, 0.333333333f, -0.5f), 1.0f);
                    v0 = lp0 - flog(u0);
                    v1 = lp1 - flog(u1);
                } else {
                    if (jb.bias) { v0 += jb.bias[col]; v1 += jb.bias[col+1]; }
                    if (jb.colS) { v0 *= jb.colS[col]; v1 *= jb.colS[col+1]; }
                    if (jb.res)  { v0 += jb.res[(size_t)rr*N + col]; v1 += jb.res[(size_t)rr*N + col + 1]; }
                }
                ssacc[mt][hh] = fmaf(v0, v0, fmaf(v1, v1, ssacc[mt][hh]));
                if (jb.C)
                    *reinterpret_cast<float2*>(&jb.C[(size_t)rr*N + col]) = make_float2(v0, v1);
                if (jb.C16) {
                    __half2 hv = __floats2half2_rn(v0, v1);
                    *reinterpret_cast<__half2*>(&jb.C16[(size_t)rr*N + col]) = hv;
                }
            }
        }
    }
    if (jb.ssOut) {
        #pragma unroll
        for (int mt = 0; mt < 2; ++mt)
            #pragma unroll
            for (int hh = 0; hh < 2; ++hh)
                atomicAdd(&jb.ssOut[m0 + wm + mt*16 + g + hh*8], ssacc[mt][hh]);
    }
}

// ---------------- tensor-core flash attention (all-f16 operands) -----------
__global__ __launch_bounds__(128)
void attn_mma(const __half* __restrict__ Qbase,
              const __half* __restrict__ Kbase, const __half* __restrict__ Vbase,
              int kvStride, int kvRowsPerBatch,
              const __half* __restrict__ Mbase, int maskStride,
              int KS, int finalWrite)
{
    int bh = blockIdx.x, split = blockIdx.y;
    int b = bh >> 3, h = bh & 7;
    int tid = threadIdx.x, w = tid >> 5, lane = tid & 31;
    int g = lane >> 2, t = lane & 3;

    const __half* Q = Qbase + (size_t)(b*QPER)*CDIM + h*DH;
    const __half* K = Kbase + (size_t)(b*kvRowsPerBatch + split*KS)*kvStride + h*DH;
    const __half* V = Vbase + (size_t)(b*kvRowsPerBatch + split*KS)*kvStride + h*DH;
    const __half* M = Mbase ? Mbase + (size_t)(b*QPER)*maskStride + split*KS : nullptr;

    __shared__ __align__(16) __half Ks[64][40];
    __shared__ __align__(16) __half Vt[32][72];

    int krow = lane & 7, kcol8 = (lane >> 3) << 3;          // K x4
    int vrow = lane & 7, vcol8 = ((lane >> 3) & 1) << 3;    // V x2

    unsigned qf[2][2][4];
    #pragma unroll
    for (int mt = 0; mt < 2; ++mt) {
        int r0 = w*32 + mt*16 + g;
        #pragma unroll
        for (int ks = 0; ks < 2; ++ks) {
            qf[mt][ks][0] = *reinterpret_cast<const unsigned*>(&Q[(size_t)r0*CDIM + ks*16 + 2*t]);
            qf[mt][ks][1] = *reinterpret_cast<const unsigned*>(&Q[(size_t)(r0+8)*CDIM + ks*16 + 2*t]);
            qf[mt][ks][2] = *reinterpret_cast<const unsigned*>(&Q[(size_t)r0*CDIM + ks*16 + 2*t + 8]);
            qf[mt][ks][3] = *reinterpret_cast<const unsigned*>(&Q[(size_t)(r0+8)*CDIM + ks*16 + 2*t + 8]);
        }
    }

    float O[2][4][4];
    #pragma unroll
    for (int mt = 0; mt < 2; ++mt)
        #pragma unroll
        for (int nd = 0; nd < 4; ++nd)
            #pragma unroll
            for (int k = 0; k < 4; ++k) O[mt][nd][k] = 0.f;
    float mrow[2][2] = {{-1e30f,-1e30f},{-1e30f,-1e30f}};
    float lrow[2][2] = {{0.f,0.f},{0.f,0.f}};

    for (int kb = 0; kb < KS; kb += 64) {
        __syncthreads();
        #pragma unroll
        for (int i = 0; i < 2; ++i) {
            int ch = tid + i*128;
            int r = ch >> 2, c = (ch & 3) << 3;
            *reinterpret_cast<float4*>(&Ks[r][c]) =
                *reinterpret_cast<const float4*>(&K[(size_t)(kb + r)*kvStride + c]);
        }
        #pragma unroll
        for (int i = 0; i < 2; ++i) {
            int ch = tid + i*128;
            int r = ch >> 2, c = (ch & 3) << 3;
            float4 raw = *reinterpret_cast<const float4*>(&V[(size_t)(kb + r)*kvStride + c]);
            const __half* hv = reinterpret_cast<const __half*>(&raw);
            #pragma unroll
            for (int jj = 0; jj < 8; ++jj) Vt[c+jj][r] = hv[jj];
        }
        __syncthreads();

        #pragma unroll
        for (int kk = 0; kk < 4; ++kk) {
            float S[2][2][4];
            #pragma unroll
            for (int mt = 0; mt < 2; ++mt)
                #pragma unroll
                for (int nt = 0; nt < 2; ++nt)
                    #pragma unroll
                    for (int k = 0; k < 4; ++k) S[mt][nt][k] = 0.f;

            #pragma unroll
            for (int nt = 0; nt < 2; ++nt) {
                unsigned kf[4];
                unsigned addr = smem_u32(&Ks[kk*16 + nt*8 + krow][kcol8]);
                LDSM_X4(kf[0], kf[1], kf[2], kf[3], addr);
                MMA_F16(S[0][nt], qf[0][0], kf[0], kf[1]);
                MMA_F16(S[0][nt], qf[0][1], kf[2], kf[3]);
                MMA_F16(S[1][nt], qf[1][0], kf[0], kf[1]);
                MMA_F16(S[1][nt], qf[1][1], kf[2], kf[3]);
            }

            if (M) {
                #pragma unroll
                for (int mt = 0; mt < 2; ++mt) {
                    int r0 = w*32 + mt*16 + g;
                    #pragma unroll
                    for (int nt = 0; nt < 2; ++nt) {
                        int c0 = kb + kk*16 + nt*8 + 2*t;
                        float2 m0 = __half22float2(*reinterpret_cast<const __half2*>(&M[(size_t)r0*maskStride + c0]));
                        float2 m1 = __half22float2(*reinterpret_cast<const __half2*>(&M[(size_t)(r0+8)*maskStride + c0]));
                        S[mt][nt][0] += m0.x; S[mt][nt][1] += m0.y;
                        S[mt][nt][2] += m1.x; S[mt][nt][3] += m1.y;
                    }
                }
            }

            #pragma unroll
            for (int mt = 0; mt < 2; ++mt) {
                #pragma unroll
                for (int hf = 0; hf < 2; ++hf) {
                    float v0 = S[mt][0][hf*2], v1 = S[mt][0][hf*2+1];
                    float v2 = S[mt][1][hf*2], v3 = S[mt][1][hf*2+1];
                    float mx = fmaxf(fmaxf(v0, v1), fmaxf(v2, v3));
                    mx = fmaxf(mx, __shfl_xor_sync(0xffffffffu, mx, 1));
                    mx = fmaxf(mx, __shfl_xor_sync(0xffffffffu, mx, 2));
                    float mnew = fmaxf(mrow[mt][hf], mx);
                    float corr = fexp(mrow[mt][hf] - mnew);
                    mrow[mt][hf] = mnew;
                    float p0 = fexp(v0 - mnew), p1 = fexp(v1 - mnew);
                    float p2 = fexp(v2 - mnew), p3 = fexp(v3 - mnew);
                    S[mt][0][hf*2] = p0; S[mt][0][hf*2+1] = p1;
                    S[mt][1][hf*2] = p2; S[mt][1][hf*2+1] = p3;
                    float ls = (p0 + p1) + (p2 + p3);
                    ls += __shfl_xor_sync(0xffffffffu, ls, 1);
                    ls += __shfl_xor_sync(0xffffffffu, ls, 2);
                    lrow[mt][hf] = lrow[mt][hf]*corr + ls;
                    #pragma unroll
                    for (int nd = 0; nd < 4; ++nd) {
                        O[mt][nd][hf*2]   *= corr;
                        O[mt][nd][hf*2+1] *= corr;
                    }
                }
            }

            unsigned pa[2][4];
            #pragma unroll
            for (int mt = 0; mt < 2; ++mt) {
                __half2 h0 = __floats2half2_rn(S[mt][0][0], S[mt][0][1]);
                __half2 h1 = __floats2half2_rn(S[mt][0][2], S[mt][0][3]);
                __half2 h2 = __floats2half2_rn(S[mt][1][0], S[mt][1][1]);
                __half2 h3 = __floats2half2_rn(S[mt][1][2], S[mt][1][3]);
                pa[mt][0] = *reinterpret_cast<unsigned*>(&h0);
                pa[mt][1] = *reinterpret_cast<unsigned*>(&h1);
                pa[mt][2] = *reinterpret_cast<unsigned*>(&h2);
                pa[mt][3] = *reinterpret_cast<unsigned*>(&h3);
            }

            #pragma unroll
            for (int nd = 0; nd < 4; ++nd) {
                unsigned vb[2];
                unsigned addr = smem_u32(&Vt[nd*8 + vrow][kk*16 + vcol8]);
                LDSM_X2(vb[0], vb[1], addr);
                MMA_F16(O[0][nd], pa[0], vb[0], vb[1]);
                MMA_F16(O[1][nd], pa[1], vb[0], vb[1]);
            }
        }
    }

    if (finalWrite) {
        #pragma unroll
        for (int mt = 0; mt < 2; ++mt) {
            #pragma unroll
            for (int hf = 0; hf < 2; ++hf) {
                float inv = 1.0f / lrow[mt][hf];
                int r = b*QPER + w*32 + mt*16 + g + hf*8;
                #pragma unroll
                for (int nd = 0; nd < 4; ++nd) {
                    __half2 o = __floats2half2_rn(O[mt][nd][hf*2]*inv, O[mt][nd][hf*2+1]*inv);
                    *reinterpret_cast<__half2*>(&g_attn16[(size_t)r*CDIM + h*DH + nd*8 + 2*t]) = o;
                }
            }
        }
    } else {
        int base = (split*64 + bh)*QPER;
        #pragma unroll
        for (int mt = 0; mt < 2; ++mt) {
            #pragma unroll
            for (int hf = 0; hf < 2; ++hf) {
                int r = w*32 + mt*16 + g + hf*8;
                if (t == 0) {
                    g_pm[base + r] = mrow[mt][hf];
                    g_pl[base + r] = lrow[mt][hf];
                }
                #pragma unroll
                for (int nd = 0; nd < 4; ++nd) {
                    __half2 o = __floats2half2_rn(O[mt][nd][hf*2], O[mt][nd][hf*2+1]);
                    *reinterpret_cast<__half2*>(&g_po16[(size_t)(base + r)*DH + nd*8 + 2*t]) = o;
                }
            }
        }
    }
}

// ---------------- split-KV combine (writes f16 attn) ------------------------
__global__ void cross_attn_combine()
{
    int qi = blockIdx.x;
    int c = threadIdx.x;
    int h = c >> 5, d = c & 31;
    int b = qi >> 7, i = qi & 127;
    int bh = b*8 + h;
    float mv[NSPLIT], lv[NSPLIT];
    float Mx = -1e30f;
    #pragma unroll
    for (int s = 0; s < NSPLIT; ++s) {
        int base = (s*64 + bh)*QPER + i;
        mv[s] = g_pm[base];
        lv[s] = g_pl[base];
        Mx = fmaxf(Mx, mv[s]);
    }
    float O = 0.f, L = 0.f;
    #pragma unroll
    for (int s = 0; s < NSPLIT; ++s) {
        float wgt = fexp(mv[s] - Mx);
        int base = (s*64 + bh)*QPER + i;
        O = fmaf(wgt, __half2float(g_po16[(size_t)base*DH + d]), O);
        L = fmaf(wgt, lv[s], L);
    }
    g_attn16[(size_t)qi*CDIM + c] = __float2half(O / L);
}

// ---------------- launch ----------------------------------------------------
static inline void* symv(const void* symbol)
{
    void* p = nullptr;
    cudaGetSymbolAddress(&p, symbol);
    return p;
}

static inline Job mkjob(const __half* A, const __half* B, const float* bias,
                        const float* res, const float* rowS, const float* rowSS,
                        float* ssOut, const float* colS,
                        float* C, __half* C16, int M, int N, int K, float scale, int mode)
{
    Job j;
    j.A = A; j.B = B; j.bias = bias; j.res = res; j.rowS = rowS; j.rowSS = rowSS;
    j.ssOut = ssOut; j.colS = colS;
    j.C = C; j.C16 = C16; j.N = N; j.K = K; j.nblocks = N/128; j.nb_total = (M/64)*(N/128);
    j.mode = mode; j.scale = scale;
    return j;
}

static inline void run_jobs(JobPack& P)
{
    int total = 0;
    for (int i = 0; i < P.njobs; ++i) total += P.jobs[i].nb_total;
    gemm_grouped<<<total, 256>>>(P);
}

extern "C" void kernel_launch(void* const* d_in, const int* in_sizes, int n_in,
                              void* d_out, int out_size)
{
    const float* q        = (const float*)d_in[0];
    const float* kv       = (const float*)d_in[1];
    const float* w_norm_kv= (const float*)d_in[4];
    const float* w_norm1  = (const float*)d_in[5];
    const float* w_norm2  = (const float*)d_in[6];
    const float* w_norm3  = (const float*)d_in[7];
    const float* wq_c     = (const float*)d_in[8];
    const float* wk_c     = (const float*)d_in[9];
    const float* wv_c     = (const float*)d_in[10];
    const float* wo_c     = (const float*)d_in[11];
    const float* bo_c     = (const float*)d_in[12];
    const float* wq_s     = (const float*)d_in[13];
    const float* wkv_s    = (const float*)d_in[14];
    const float* wo_s     = (const float*)d_in[15];
    const float* bo_s     = (const float*)d_in[16];
    const float* w1_mlp   = (const float*)d_in[17];
    const float* b1_mlp   = (const float*)d_in[18];
    const float* w2_mlp   = (const float*)d_in[19];
    const float* b2_mlp   = (const float*)d_in[20];
    const float* w1_mask  = (const float*)d_in[21];
    const float* b1_mask  = (const float*)d_in[22];
    const float* w2_mask  = (const float*)d_in[23];
    const float* b2_mask  = (const float*)d_in[24];
    float* out = (float*)d_out;

    __half* p_Kc16 = (__half*)symv(g_Kc16);
    __half* p_Vc16 = (__half*)symv(g_Vc16);
    __half* p_mh16 = (__half*)symv(g_mh16);
    __half* p_mk16 = (__half*)symv(g_mk16);
    __half* p_z16  = (__half*)symv(g_z16);
    __half* p_Qc16 = (__half*)symv(g_Qc16);
    __half* p_at16 = (__half*)symv(g_attn16);
    float*  p_q1   = (float*) symv(g_q1);
    __half* p_q116 = (__half*)symv(g_q116);
    float*  p_q2   = (float*) symv(g_q2);
    __half* p_q216 = (__half*)symv(g_q216);
    __half* p_Qs16 = (__half*)symv(g_Qs16);
    __half* p_KVs16= (__half*)symv(g_KVs16);
    __half* p_hid16= (__half*)symv(g_hid16);
    __half* p_wqc  = (__half*)symv(g_wqc16);
    __half* p_wkc  = (__half*)symv(g_wkc16);
    __half* p_wvc  = (__half*)symv(g_wvc16);
    __half* p_wqs  = (__half*)symv(g_wqs16);
    __half* p_wkvs = (__half*)symv(g_wkvs16);
    __half* p_w1   = (__half*)symv(g_w116);
    __half* p_w1m  = (__half*)symv(g_w1m16);
    __half* p_w2m  = (__half*)symv(g_w2m16);
    __half* p_woc  = (__half*)symv(g_woc16);
    __half* p_wos  = (__half*)symv(g_wos16);
    __half* p_w2   = (__half*)symv(g_w216);
    __half* p_q16  = (__half*)symv(g_q16);
    __half* p_kv16 = (__half*)symv(g_kv16);
    float*  p_skv  = (float*) symv(g_skv);
    float*  p_sq   = (float*) symv(g_sq);
    float*  p_ssq1 = (float*) symv(g_ssq1);
    float*  p_ssq2 = (float*) symv(g_ssq2);

    // L1: vectorized convert + row scales + zero ssq
    prep<<<PREP_A + PREP_B + PREP_C, 256>>>(
        wq_c, wk_c, wv_c, wq_s, wkv_s, w1_mlp,
        w1_mask, w2_mask, wo_c, wo_s, w2_mlp,
        w_norm1, w_norm_kv, w_norm2, w_norm3, kv, q);
    // L2: mh = gelu(q @ w1m^T + b1)
    {
        JobPack P; P.njobs = 1;
        P.jobs[0] = mkjob(p_q16, p_w1m, b1_mask, nullptr, nullptr, nullptr, nullptr, nullptr,
                          nullptr, p_mh16, NQ, CDIM, CDIM, 1.f, 1);
        run_jobs(P);
    }
    // L3: mk = (mh @ w2m^T + b2) ∘ w_norm_kv
    {
        JobPack P; P.njobs = 1;
        P.jobs[0] = mkjob(p_mh16, p_w2m, b2_mask, nullptr, nullptr, nullptr, nullptr, w_norm_kv,
                          nullptr, p_mk16, NQ, CDIM, CDIM, 1.f, 0);
        run_jobs(P);
    }
    // L4: BIG — Kc, Vc, Qc, zT(8 batches) in one launch
    {
        JobPack P; P.njobs = 11;
        P.jobs[0] = mkjob(p_kv16, p_wkc, nullptr, nullptr, p_skv, nullptr, nullptr, nullptr,
                          nullptr, p_Kc16, NKV, CDIM, CDIM, 1.f, 0);
        P.jobs[1] = mkjob(p_kv16, p_wvc, nullptr, nullptr, p_skv, nullptr, nullptr, nullptr,
                          nullptr, p_Vc16, NKV, CDIM, CDIM, 1.f, 0);
        P.jobs[2] = mkjob(p_q16, p_wqc, nullptr, nullptr, p_sq, nullptr, nullptr, nullptr,
                          nullptr, p_Qc16, NQ, CDIM, CDIM, ATTN_SCALE, 0);
        for (int b = 0; b < BATCH; ++b)
            P.jobs[3+b] = mkjob(p_mk16 + (size_t)b*QPER*CDIM, p_kv16 + (size_t)b*KVPER*CDIM,
                                nullptr, nullptr, nullptr, nullptr, nullptr, p_skv + b*KVPER,
                                nullptr, p_z16 + (size_t)b*QPER*KVPER, QPER, KVPER, CDIM, 1.f, 2);
        run_jobs(P);
    }
    // L5: cross attention (split-KV partials, all-f16 operands)
    attn_mma<<<dim3(64, NSPLIT), 128>>>(p_Qc16, p_Kc16, p_Vc16, CDIM, KVPER,
                                        p_z16, KVPER, KVPER/NSPLIT, 0);
    // L6: combine -> attn16
    cross_attn_combine<<<NQ, CDIM>>>();
    // L7: q1 = q + attn @ wo_c^T + bo_c  (+ssq1, f16 shadow)
    {
        JobPack P; P.njobs = 1;
        P.jobs[0] = mkjob(p_at16, p_woc, bo_c, q, nullptr, nullptr, p_ssq1, nullptr,
                          p_q1, p_q116, NQ, CDIM, CDIM, 1.f, 0);
        run_jobs(P);
    }
    // L8: Qs + KVs (rms via ssq1, f16 out)
    {
        JobPack P; P.njobs = 2;
        P.jobs[0] = mkjob(p_q116, p_wqs, nullptr, nullptr, nullptr, p_ssq1, nullptr, nullptr,
                          nullptr, p_Qs16, NQ, CDIM, CDIM, ATTN_SCALE, 0);
        P.jobs[1] = mkjob(p_q116, p_wkvs, nullptr, nullptr, nullptr, p_ssq1, nullptr, nullptr,
                          nullptr, p_KVs16, NQ, 2*CDIM, CDIM, 1.f, 0);
        run_jobs(P);
    }
    // L9: self attention (direct f16 write)
    attn_mma<<<dim3(64, 1), 128>>>(p_Qs16, p_KVs16, p_KVs16 + CDIM, 2*CDIM, QPER,
                                   nullptr, 0, QPER, 1);
    // L10: q2 = q1 + attn @ wo_s^T + bo_s  (+ssq2, f16 shadow)
    {
        JobPack P; P.njobs = 1;
        P.jobs[0] = mkjob(p_at16, p_wos, bo_s, p_q1, nullptr, nullptr, p_ssq2, nullptr,
                          p_q2, p_q216, NQ, CDIM, CDIM, 1.f, 0);
        run_jobs(P);
    }
    // L11: hid = gelu(rms(q2) @ w1'^T + b1)  (f16 only)
    {
        JobPack P; P.njobs = 1;
        P.jobs[0] = mkjob(p_q216, p_w1, b1_mlp, nullptr, nullptr, p_ssq2, nullptr, nullptr,
                          nullptr, p_hid16, NQ, 4*CDIM, CDIM, 1.f, 1);
        run_jobs(P);
    }
    // L12: out = q2 + hid @ w2^T + b2
    {
        JobPack P; P.njobs = 1;
        P.jobs[0] = mkjob(p_hid16, p_w2, b2_mlp, p_q2, nullptr, nullptr, nullptr, nullptr,
                          out, nullptr, NQ, CDIM, 4*CDIM, 1.f, 0);
        run_jobs(P);
    }
}

// round 17
// speedup vs baseline: 1.2341x; 1.2341x over previous
#include <cuda_runtime.h>
#include <cuda_bf16.h>
#include <cuda_fp16.h>
#include <cstdint>
#include <math.h>

// ---------------- problem constants ----------------
#define CDIM 256
#define HEADS 8
#define DH 32
#define BATCH 8
#define QPER 128
#define KVPER 1024
#define NQ (BATCH*QPER)      // 1024
#define NKV (BATCH*KVPER)    // 8192
#define RMS_EPS 1.1920928955078125e-07f
#define ATTN_SCALE 0.17677669529663687f  // 1/sqrt(32)
#define NSPLIT 4             // cross-attn key splits

// ---------------- scratch (device globals; no cudaMalloc allowed) ----------
__device__ __align__(16) __half g_Kc16[NKV*CDIM];
__device__ __align__(16) __half g_Vc16[NKV*CDIM];
__device__ __align__(16) __half g_mh16[NQ*CDIM];
__device__ __align__(16) __half g_mk16[NQ*CDIM];       // mk with w_norm_kv folded
__device__ __align__(16) __half g_z16[NQ*KVPER];       // mask logits [q][kv_local]
__device__ __align__(16) __half g_Qc16[NQ*CDIM];
__device__ __align__(16) __half g_attn16[NQ*CDIM];
__device__ __align__(16) float  g_q1 [NQ*CDIM];
__device__ __align__(16) __half g_q116[NQ*CDIM];
__device__ __align__(16) float  g_q2 [NQ*CDIM];
__device__ __align__(16) __half g_q216[NQ*CDIM];
__device__ __align__(16) __half g_Qs16[NQ*CDIM];
__device__ __align__(16) __half g_KVs16[NQ*2*CDIM];
__device__ __align__(16) __half g_hid16[NQ*4*CDIM];
__device__ __align__(16) __half g_po16[NSPLIT*64*QPER*DH];
__device__ __align__(16) float  g_pm [NSPLIT*64*QPER];
__device__ __align__(16) float  g_pl [NSPLIT*64*QPER];
// f16 weights (folded where applicable) and f16 inputs
__device__ __align__(16) __half g_wqc16 [CDIM*CDIM];
__device__ __align__(16) __half g_wkc16 [CDIM*CDIM];
__device__ __align__(16) __half g_wvc16 [CDIM*CDIM];
__device__ __align__(16) __half g_wqs16 [CDIM*CDIM];
__device__ __align__(16) __half g_wkvs16[2*CDIM*CDIM];
__device__ __align__(16) __half g_w116  [4*CDIM*CDIM];
__device__ __align__(16) __half g_w1m16 [CDIM*CDIM];
__device__ __align__(16) __half g_w2m16 [CDIM*CDIM];
__device__ __align__(16) __half g_woc16 [CDIM*CDIM];
__device__ __align__(16) __half g_wos16 [CDIM*CDIM];
__device__ __align__(16) __half g_w216  [CDIM*4*CDIM];
__device__ __align__(16) __half g_q16   [NQ*CDIM];
__device__ __align__(16) __half g_kv16  [NKV*CDIM];
// per-row inv-rms scales / sum-of-squares
__device__ float g_skv [NKV];
__device__ float g_sq  [NQ];
__device__ float g_ssq1[NQ];
__device__ float g_ssq2[NQ];

// ---------------- fast exp / log (FMA-pipe polys, no MUFU) -----------------
__device__ __forceinline__ float fexp(float x) {
    float y = x * 1.44269504088896340736f;
    y = fminf(fmaxf(y, -126.0f), 126.0f);
    float r = rintf(y);
    float f = y - r;
    float p = 1.3333558146428443e-3f;
    p = fmaf(p, f, 9.6181291076284772e-3f);
    p = fmaf(p, f, 5.5504108664821580e-2f);
    p = fmaf(p, f, 2.4022650695910072e-1f);
    p = fmaf(p, f, 6.9314718055994531e-1f);
    p = fmaf(p, f, 1.0f);
    float s = __int_as_float(((int)r + 127) << 23);
    return p * s;
}

__device__ __forceinline__ float flog(float x) {
    int ix = __float_as_int(x);
    int e = (ix - 0x3f3504f3) >> 23;
    float m = __int_as_float(ix - (e << 23));
    float f = m - 1.0f;
    float z = f * f;
    float p = 7.0376836292e-2f;
    p = fmaf(p, f, -1.1514610310e-1f);
    p = fmaf(p, f,  1.1676998740e-1f);
    p = fmaf(p, f, -1.2420140846e-1f);
    p = fmaf(p, f,  1.4249322787e-1f);
    p = fmaf(p, f, -1.6668057665e-1f);
    p = fmaf(p, f,  2.0000714765e-1f);
    p = fmaf(p, f, -2.4999993993e-1f);
    p = fmaf(p, f,  3.3333331174e-1f);
    float y = f * z * p;
    y = fmaf(-0.5f, z, y);
    return fmaf((float)e, 0.693147180559945f, f + y);
}

// ---------------- ldmatrix helpers ------------------------------------------
#define LDSM_X4(r0, r1, r2, r3, addr) \
    asm volatile("ldmatrix.sync.aligned.m8n8.x4.shared.b16 {%0,%1,%2,%3}, [%4];" \
        : "=r"(r0), "=r"(r1), "=r"(r2), "=r"(r3) : "r"(addr))
#define LDSM_X2(r0, r1, addr) \
    asm volatile("ldmatrix.sync.aligned.m8n8.x2.shared.b16 {%0,%1}, [%2];" \
        : "=r"(r0), "=r"(r1) : "r"(addr))

__device__ __forceinline__ unsigned smem_u32(const void* p) {
    return (unsigned)__cvta_generic_to_shared(p);
}

// ---------------- prep (vectorized): weights cvt + q/kv cvt + row rms + zero
#define PREP_A 1152
#define PREP_B 2304
#define PREP_C 8
__global__ __launch_bounds__(256)
void prep(const float* __restrict__ wq_c, const float* __restrict__ wk_c,
          const float* __restrict__ wv_c, const float* __restrict__ wq_s,
          const float* __restrict__ wkv_s, const float* __restrict__ w1,
          const float* __restrict__ w1m, const float* __restrict__ w2m,
          const float* __restrict__ woc, const float* __restrict__ wos,
          const float* __restrict__ w2,
          const float* __restrict__ n1, const float* __restrict__ nkv,
          const float* __restrict__ n2, const float* __restrict__ n3,
          const float* __restrict__ kv, const float* __restrict__ q)
{
    int bid = blockIdx.x;
    int tid = threadIdx.x;
    if (bid < PREP_A) {
        int i = bid*1024 + tid*4;
        const float* src; __half* dst; const float* nrm; int off;
        if      (i <   65536) { src=wq_c;  dst=g_wqc16;  nrm=n1;     off=0; }
        else if (i <  131072) { src=wk_c;  dst=g_wkc16;  nrm=nkv;    off=65536; }
        else if (i <  196608) { src=wv_c;  dst=g_wvc16;  nrm=nkv;    off=131072; }
        else if (i <  262144) { src=wq_s;  dst=g_wqs16;  nrm=n2;     off=196608; }
        else if (i <  393216) { src=wkv_s; dst=g_wkvs16; nrm=n2;     off=262144; }
        else if (i <  655360) { src=w1;    dst=g_w116;   nrm=n3;     off=393216; }
        else if (i <  720896) { src=w1m;   dst=g_w1m16;  nrm=nullptr;off=655360; }
        else if (i <  786432) { src=w2m;   dst=g_w2m16;  nrm=nullptr;off=720896; }
        else if (i <  851968) { src=woc;   dst=g_woc16;  nrm=nullptr;off=786432; }
        else if (i <  917504) { src=wos;   dst=g_wos16;  nrm=nullptr;off=851968; }
        else                  { src=w2;    dst=g_w216;   nrm=nullptr;off=917504; }
        int j = i - off;
        float4 v = *reinterpret_cast<const float4*>(&src[j]);
        if (nrm) {
            int k = j & 255;
            v.x *= nrm[k]; v.y *= nrm[k+1]; v.z *= nrm[k+2]; v.w *= nrm[k+3];
        }
        __half2 h0 = __floats2half2_rn(v.x, v.y);
        __half2 h1 = __floats2half2_rn(v.z, v.w);
        *reinterpret_cast<__half2*>(&dst[j])   = h0;
        *reinterpret_cast<__half2*>(&dst[j+2]) = h1;
    } else if (bid < PREP_A + PREP_B) {
        int rbase = (bid - PREP_A) * 4;
        int rloc = tid >> 6;
        int col = (tid & 63) * 4;
        int r = rbase + rloc;
        const float* src; __half* dst;
        if (r < NQ) { src = q + (size_t)r*CDIM; dst = g_q16 + (size_t)r*CDIM; }
        else { int rr = r - NQ; src = kv + (size_t)rr*CDIM; dst = g_kv16 + (size_t)rr*CDIM; }
        float4 v = *reinterpret_cast<const float4*>(&src[col]);
        __half2 h0 = __floats2half2_rn(v.x, v.y);
        __half2 h1 = __floats2half2_rn(v.z, v.w);
        *reinterpret_cast<__half2*>(&dst[col])   = h0;
        *reinterpret_cast<__half2*>(&dst[col+2]) = h1;
        float ss = fmaf(v.x, v.x, fmaf(v.y, v.y, fmaf(v.z, v.z, v.w*v.w)));
        #pragma unroll
        for (int o = 16; o > 0; o >>= 1) ss += __shfl_xor_sync(0xffffffffu, ss, o);
        __shared__ float red[8];
        if ((tid & 31) == 0) red[tid >> 5] = ss;
        __syncthreads();
        if (tid < 4) {
            float s = red[2*tid] + red[2*tid+1];
            float inv = rsqrtf(s*(1.0f/CDIM) + RMS_EPS);
            int rw = rbase + tid;
            if (rw < NQ) g_sq[rw] = inv;
            else         g_skv[rw - NQ] = inv;
        }
    } else {
        int i = (bid - PREP_A - PREP_B)*256 + tid;
        if (i < NQ) g_ssq1[i] = 0.f;
        else        g_ssq2[i - NQ] = 0.f;
    }
}

// ---------------- job plumbing ----------------------------------------------
#define MAXJOBS 11

struct Job {
    const __half *A, *B;
    const float *bias, *res, *rowS, *rowSS, *colS;
    float *C; __half *C16; float *ssOut;
    int N, K, nblocks, nb_total, mode;
    float scale;
};
struct JobPack { Job jobs[MAXJOBS]; int njobs; };

__device__ __forceinline__ void cp_async16(void* smem, const void* gmem) {
    unsigned s = (unsigned)__cvta_generic_to_shared(smem);
    asm volatile("cp.async.cg.shared.global [%0], [%1], 16;\n" :: "r"(s), "l"(gmem));
}
#define CP_COMMIT() asm volatile("cp.async.commit_group;\n" ::: "memory")
#define CP_WAIT1()  asm volatile("cp.async.wait_group 1;\n" ::: "memory")

#define MMA_F16(acc, a, b0, b1) \
    asm volatile("mma.sync.aligned.m16n8k16.row.col.f32.f16.f16.f32 " \
        "{%0,%1,%2,%3}, {%4,%5,%6,%7}, {%8,%9}, {%0,%1,%2,%3};" \
        : "+f"(acc[0]), "+f"(acc[1]), "+f"(acc[2]), "+f"(acc[3]) \
        : "r"(a[0]), "r"(a[1]), "r"(a[2]), "r"(a[3]), "r"(b0), "r"(b1))

// shared epilogue scalar op
__device__ __forceinline__ void epi2(const Job& jb, int rr, int col, int N,
                                     float& v0, float& v1)
{
    if (jb.mode == 1) {
        v0 += jb.bias[col];   v1 += jb.bias[col+1];
        v0 = 0.5f * v0 * (1.0f + erff(v0 * 0.70710678118654752f));
        v1 = 0.5f * v1 * (1.0f + erff(v1 * 0.70710678118654752f));
    } else if (jb.mode == 2) {
        if (jb.colS) { v0 *= jb.colS[col]; v1 *= jb.colS[col+1]; }
        float u0 = 1.0f + fexp(-v0);
        float u1 = 1.0f + fexp(-v1);
        float w0 = 1e-6f*u0, w1 = 1e-6f*u1;
        float lp0 = w0*fmaf(w0, fmaf(w0, 0.333333333f, -0.5f), 1.0f);
        float lp1 = w1*fmaf(w1, fmaf(w1, 0.333333333f, -0.5f), 1.0f);
        v0 = lp0 - flog(u0);
        v1 = lp1 - flog(u1);
    } else {
        if (jb.bias) { v0 += jb.bias[col]; v1 += jb.bias[col+1]; }
        if (jb.colS) { v0 *= jb.colS[col]; v1 *= jb.colS[col+1]; }
        if (jb.res)  { v0 += jb.res[(size_t)rr*N + col]; v1 += jb.res[(size_t)rr*N + col + 1]; }
    }
}

// ---------------- small grouped GEMM: BM=32, BN=64, BK=128, 128 thr --------
#define BKS 128
#define PADS 136
__global__ __launch_bounds__(128)
void gemm_sm(JobPack P)
{
    int bid = blockIdx.x;
    int j = 0;
    #pragma unroll 1
    while (j < P.njobs - 1 && bid >= P.jobs[j].nb_total) { bid -= P.jobs[j].nb_total; ++j; }
    const Job jb = P.jobs[j];

    int xb = bid % jb.nblocks, yb = bid / jb.nblocks;
    int m0 = yb * 32, n0 = xb * 64;
    const __half* A = jb.A;
    const __half* B = jb.B;
    int K = jb.K;

    __shared__ __align__(16) __half As[2][32][PADS];
    __shared__ __align__(16) __half Bs[2][64][PADS];

    int tid = threadIdx.x;
    int warp = tid >> 5, lane = tid & 31;
    int wn = warp * 16;
    int g = lane >> 2, t = lane & 3;

    int arow = lane & 15, acol8 = (lane >> 4) << 3;
    int brow = lane & 7,  bcol8 = ((lane >> 3) & 1) << 3;

    float acc[2][2][4];
    #pragma unroll
    for (int i = 0; i < 2; ++i)
        #pragma unroll
        for (int jj = 0; jj < 2; ++jj)
            #pragma unroll
            for (int k = 0; k < 4; ++k) acc[i][jj][k] = 0.f;

    auto load_stage = [&](int st, int kk) {
        #pragma unroll
        for (int i = 0; i < 12; ++i) {
            int ch = tid + i*128;
            if (ch < 512) {
                int r = ch >> 4, c = (ch & 15) << 3;
                cp_async16(&As[st][r][c], &A[(size_t)(m0 + r)*K + kk + c]);
            } else {
                int ch2 = ch - 512;
                int r = ch2 >> 4, c = (ch2 & 15) << 3;
                cp_async16(&Bs[st][r][c], &B[(size_t)(n0 + r)*K + kk + c]);
            }
        }
    };

    int NIT = K >> 7;
    load_stage(0, 0);
    CP_COMMIT();
    if (NIT > 1) load_stage(1, BKS);
    CP_COMMIT();

    for (int it = 0; it < NIT; ++it) {
        CP_WAIT1();
        __syncthreads();
        int st = it & 1;
        #pragma unroll
        for (int ks = 0; ks < 8; ++ks) {
            int kb = ks * 16;
            unsigned af[2][4], bf[2][2];
            #pragma unroll
            for (int mt = 0; mt < 2; ++mt) {
                unsigned addr = smem_u32(&As[st][mt*16 + arow][kb + acol8]);
                LDSM_X4(af[mt][0], af[mt][1], af[mt][2], af[mt][3], addr);
            }
            #pragma unroll
            for (int nt = 0; nt < 2; ++nt) {
                unsigned addr = smem_u32(&Bs[st][wn + nt*8 + brow][kb + bcol8]);
                LDSM_X2(bf[nt][0], bf[nt][1], addr);
            }
            #pragma unroll
            for (int mt = 0; mt < 2; ++mt)
                #pragma unroll
                for (int nt = 0; nt < 2; ++nt)
                    MMA_F16(acc[mt][nt], af[mt], bf[nt][0], bf[nt][1]);
        }
        __syncthreads();
        if (it + 2 < NIT) load_stage(st, (it+2)*BKS);
        CP_COMMIT();
    }

    int N = jb.N;
    float ssacc[2][2] = {{0.f,0.f},{0.f,0.f}};
    #pragma unroll
    for (int mt = 0; mt < 2; ++mt) {
        #pragma unroll
        for (int nt = 0; nt < 2; ++nt) {
            float* cc = acc[mt][nt];
            int row = m0 + mt*16 + g;
            int col = n0 + wn + nt*8 + 2*t;
            #pragma unroll
            for (int hh = 0; hh < 2; ++hh) {
                int rr = row + hh*8;
                float rs = 1.0f;
                if (jb.rowSS)     rs = rsqrtf(jb.rowSS[rr]*(1.0f/CDIM) + RMS_EPS);
                else if (jb.rowS) rs = jb.rowS[rr];
                float v0 = cc[hh*2+0] * jb.scale * rs;
                float v1 = cc[hh*2+1] * jb.scale * rs;
                epi2(jb, rr, col, N, v0, v1);
                ssacc[mt][hh] = fmaf(v0, v0, fmaf(v1, v1, ssacc[mt][hh]));
                if (jb.C)
                    *reinterpret_cast<float2*>(&jb.C[(size_t)rr*N + col]) = make_float2(v0, v1);
                if (jb.C16) {
                    __half2 hv = __floats2half2_rn(v0, v1);
                    *reinterpret_cast<__half2*>(&jb.C16[(size_t)rr*N + col]) = hv;
                }
            }
        }
    }
    if (jb.ssOut) {
        #pragma unroll
        for (int mt = 0; mt < 2; ++mt)
            #pragma unroll
            for (int hh = 0; hh < 2; ++hh)
                atomicAdd(&jb.ssOut[m0 + mt*16 + g + hh*8], ssacc[mt][hh]);
    }
}

// ---------------- big grouped GEMM: BM=64, BN=128, BK=64, 256 thr ----------
#define BKB 64
#define PADB 72
__global__ __launch_bounds__(256)
void gemm_big(JobPack P)
{
    int bid = blockIdx.x;
    int j = 0;
    #pragma unroll 1
    while (j < P.njobs - 1 && bid >= P.jobs[j].nb_total) { bid -= P.jobs[j].nb_total; ++j; }
    const Job jb = P.jobs[j];

    int xb = bid % jb.nblocks, yb = bid / jb.nblocks;
    int m0 = yb * 64, n0 = xb * 128;
    const __half* A = jb.A;
    const __half* B = jb.B;
    int K = jb.K;

    __shared__ __align__(16) __half As[2][64][PADB];
    __shared__ __align__(16) __half Bs[2][128][PADB];

    int tid = threadIdx.x;
    int warp = tid >> 5, lane = tid & 31;
    int wm = (warp >> 2) * 32;
    int wn = (warp & 3) * 32;
    int g = lane >> 2, t = lane & 3;

    int arow = lane & 15, acol8 = (lane >> 4) << 3;
    int brow = lane & 7,  bcol8 = ((lane >> 3) & 1) << 3;

    float acc[2][4][4];
    #pragma unroll
    for (int i = 0; i < 2; ++i)
        #pragma unroll
        for (int jj = 0; jj < 4; ++jj)
            #pragma unroll
            for (int k = 0; k < 4; ++k) acc[i][jj][k] = 0.f;

    auto load_stage = [&](int st, int kk) {
        #pragma unroll
        for (int i = 0; i < 6; ++i) {
            int ch = tid + i*256;
            if (ch < 512) {
                int r = ch >> 3, c = (ch & 7) << 3;
                cp_async16(&As[st][r][c], &A[(size_t)(m0 + r)*K + kk + c]);
            } else {
                int ch2 = ch - 512;
                int r = ch2 >> 3, c = (ch2 & 7) << 3;
                cp_async16(&Bs[st][r][c], &B[(size_t)(n0 + r)*K + kk + c]);
            }
        }
    };

    int NIT = K >> 6;
    load_stage(0, 0);
    CP_COMMIT();
    if (NIT > 1) load_stage(1, BKB);
    CP_COMMIT();

    for (int it = 0; it < NIT; ++it) {
        CP_WAIT1();
        __syncthreads();
        int st = it & 1;
        #pragma unroll
        for (int ks = 0; ks < 4; ++ks) {
            int kb = ks * 16;
            unsigned af[2][4], bf[4][2];
            #pragma unroll
            for (int mt = 0; mt < 2; ++mt) {
                unsigned addr = smem_u32(&As[st][wm + mt*16 + arow][kb + acol8]);
                LDSM_X4(af[mt][0], af[mt][1], af[mt][2], af[mt][3], addr);
            }
            #pragma unroll
            for (int nt = 0; nt < 4; ++nt) {
                unsigned addr = smem_u32(&Bs[st][wn + nt*8 + brow][kb + bcol8]);
                LDSM_X2(bf[nt][0], bf[nt][1], addr);
            }
            #pragma unroll
            for (int mt = 0; mt < 2; ++mt)
                #pragma unroll
                for (int nt = 0; nt < 4; ++nt)
                    MMA_F16(acc[mt][nt], af[mt], bf[nt][0], bf[nt][1]);
        }
        __syncthreads();
        if (it + 2 < NIT) load_stage(st, (it+2)*BKB);
        CP_COMMIT();
    }

    int N = jb.N;
    float ssacc[2][2] = {{0.f,0.f},{0.f,0.f}};
    #pragma unroll
    for (int mt = 0; mt < 2; ++mt) {
        #pragma unroll
        for (int nt = 0; nt < 4; ++nt) {
            float* cc = acc[mt][nt];
            int row = m0 + wm + mt*16 + g;
            int col = n0 + wn + nt*8 + 2*t;
            #pragma unroll
            for (int hh = 0; hh < 2; ++hh) {
                int rr = row + hh*8;
                float rs = 1.0f;
                if (jb.rowSS)     rs = rsqrtf(jb.rowSS[rr]*(1.0f/CDIM) + RMS_EPS);
                else if (jb.rowS) rs = jb.rowS[rr];
                float v0 = cc[hh*2+0] * jb.scale * rs;
                float v1 = cc[hh*2+1] * jb.scale * rs;
                epi2(jb, rr, col, N, v0, v1);
                ssacc[mt][hh] = fmaf(v0, v0, fmaf(v1, v1, ssacc[mt][hh]));
                if (jb.C)
                    *reinterpret_cast<float2*>(&jb.C[(size_t)rr*N + col]) = make_float2(v0, v1);
                if (jb.C16) {
                    __half2 hv = __floats2half2_rn(v0, v1);
                    *reinterpret_cast<__half2*>(&jb.C16[(size_t)rr*N + col]) = hv;
                }
            }
        }
    }
    if (jb.ssOut) {
        #pragma unroll
        for (int mt = 0; mt < 2; ++mt)
            #pragma unroll
            for (int hh = 0; hh < 2; ++hh)
                atomicAdd(&jb.ssOut[m0 + wm + mt*16 + g + hh*8], ssacc[mt][hh]);
    }
}

// ---------------- tensor-core flash attention (all-f16 operands) -----------
__global__ __launch_bounds__(128)
void attn_mma(const __half* __restrict__ Qbase,
              const __half* __restrict__ Kbase, const __half* __restrict__ Vbase,
              int kvStride, int kvRowsPerBatch,
              const __half* __restrict__ Mbase, int maskStride,
              int KS, int finalWrite)
{
    int bh = blockIdx.x, split = blockIdx.y;
    int b = bh >> 3, h = bh & 7;
    int tid = threadIdx.x, w = tid >> 5, lane = tid & 31;
    int g = lane >> 2, t = lane & 3;

    const __half* Q = Qbase + (size_t)(b*QPER)*CDIM + h*DH;
    const __half* K = Kbase + (size_t)(b*kvRowsPerBatch + split*KS)*kvStride + h*DH;
    const __half* V = Vbase + (size_t)(b*kvRowsPerBatch + split*KS)*kvStride + h*DH;
    const __half* M = Mbase ? Mbase + (size_t)(b*QPER)*maskStride + split*KS : nullptr;

    __shared__ __align__(16) __half Ks[64][40];
    __shared__ __align__(16) __half Vt[32][72];

    int krow = lane & 7, kcol8 = (lane >> 3) << 3;
    int vrow = lane & 7, vcol8 = ((lane >> 3) & 1) << 3;

    unsigned qf[2][2][4];
    #pragma unroll
    for (int mt = 0; mt < 2; ++mt) {
        int r0 = w*32 + mt*16 + g;
        #pragma unroll
        for (int ks = 0; ks < 2; ++ks) {
            qf[mt][ks][0] = *reinterpret_cast<const unsigned*>(&Q[(size_t)r0*CDIM + ks*16 + 2*t]);
            qf[mt][ks][1] = *reinterpret_cast<const unsigned*>(&Q[(size_t)(r0+8)*CDIM + ks*16 + 2*t]);
            qf[mt][ks][2] = *reinterpret_cast<const unsigned*>(&Q[(size_t)r0*CDIM + ks*16 + 2*t + 8]);
            qf[mt][ks][3] = *reinterpret_cast<const unsigned*>(&Q[(size_t)(r0+8)*CDIM + ks*16 + 2*t + 8]);
        }
    }

    float O[2][4][4];
    #pragma unroll
    for (int mt = 0; mt < 2; ++mt)
        #pragma unroll
        for (int nd = 0; nd < 4; ++nd)
            #pragma unroll
            for (int k = 0; k < 4; ++k) O[mt][nd][k] = 0.f;
    float mrow[2][2] = {{-1e30f,-1e30f},{-1e30f,-1e30f}};
    float lrow[2][2] = {{0.f,0.f},{0.f,0.f}};

    for (int kb = 0; kb < KS; kb += 64) {
        __syncthreads();
        #pragma unroll
        for (int i = 0; i < 2; ++i) {
            int ch = tid + i*128;
            int r = ch >> 2, c = (ch & 3) << 3;
            *reinterpret_cast<float4*>(&Ks[r][c]) =
                *reinterpret_cast<const float4*>(&K[(size_t)(kb + r)*kvStride + c]);
        }
        #pragma unroll
        for (int i = 0; i < 2; ++i) {
            int ch = tid + i*128;
            int r = ch >> 2, c = (ch & 3) << 3;
            float4 raw = *reinterpret_cast<const float4*>(&V[(size_t)(kb + r)*kvStride + c]);
            const __half* hv = reinterpret_cast<const __half*>(&raw);
            #pragma unroll
            for (int jj = 0; jj < 8; ++jj) Vt[c+jj][r] = hv[jj];
        }
        __syncthreads();

        #pragma unroll
        for (int kk = 0; kk < 4; ++kk) {
            float S[2][2][4];
            #pragma unroll
            for (int mt = 0; mt < 2; ++mt)
                #pragma unroll
                for (int nt = 0; nt < 2; ++nt)
                    #pragma unroll
                    for (int k = 0; k < 4; ++k) S[mt][nt][k] = 0.f;

            #pragma unroll
            for (int nt = 0; nt < 2; ++nt) {
                unsigned kf[4];
                unsigned addr = smem_u32(&Ks[kk*16 + nt*8 + krow][kcol8]);
                LDSM_X4(kf[0], kf[1], kf[2], kf[3], addr);
                MMA_F16(S[0][nt], qf[0][0], kf[0], kf[1]);
                MMA_F16(S[0][nt], qf[0][1], kf[2], kf[3]);
                MMA_F16(S[1][nt], qf[1][0], kf[0], kf[1]);
                MMA_F16(S[1][nt], qf[1][1], kf[2], kf[3]);
            }

            if (M) {
                #pragma unroll
                for (int mt = 0; mt < 2; ++mt) {
                    int r0 = w*32 + mt*16 + g;
                    #pragma unroll
                    for (int nt = 0; nt < 2; ++nt) {
                        int c0 = kb + kk*16 + nt*8 + 2*t;
                        float2 m0 = __half22float2(*reinterpret_cast<const __half2*>(&M[(size_t)r0*maskStride + c0]));
                        float2 m1 = __half22float2(*reinterpret_cast<const __half2*>(&M[(size_t)(r0+8)*maskStride + c0]));
                        S[mt][nt][0] += m0.x; S[mt][nt][1] += m0.y;
                        S[mt][nt][2] += m1.x; S[mt][nt][3] += m1.y;
                    }
                }
            }

            #pragma unroll
            for (int mt = 0; mt < 2; ++mt) {
                #pragma unroll
                for (int hf = 0; hf < 2; ++hf) {
                    float v0 = S[mt][0][hf*2], v1 = S[mt][0][hf*2+1];
                    float v2 = S[mt][1][hf*2], v3 = S[mt][1][hf*2+1];
                    float mx = fmaxf(fmaxf(v0, v1), fmaxf(v2, v3));
                    mx = fmaxf(mx, __shfl_xor_sync(0xffffffffu, mx, 1));
                    mx = fmaxf(mx, __shfl_xor_sync(0xffffffffu, mx, 2));
                    float mnew = fmaxf(mrow[mt][hf], mx);
                    float corr = fexp(mrow[mt][hf] - mnew);
                    mrow[mt][hf] = mnew;
                    float p0 = fexp(v0 - mnew), p1 = fexp(v1 - mnew);
                    float p2 = fexp(v2 - mnew), p3 = fexp(v3 - mnew);
                    S[mt][0][hf*2] = p0; S[mt][0][hf*2+1] = p1;
                    S[mt][1][hf*2] = p2; S[mt][1][hf*2+1] = p3;
                    float ls = (p0 + p1) + (p2 + p3);
                    ls += __shfl_xor_sync(0xffffffffu, ls, 1);
                    ls += __shfl_xor_sync(0xffffffffu, ls, 2);
                    lrow[mt][hf] = lrow[mt][hf]*corr + ls;
                    #pragma unroll
                    for (int nd = 0; nd < 4; ++nd) {
                        O[mt][nd][hf*2]   *= corr;
                        O[mt][nd][hf*2+1] *= corr;
                    }
                }
            }

            unsigned pa[2][4];
            #pragma unroll
            for (int mt = 0; mt < 2; ++mt) {
                __half2 h0 = __floats2half2_rn(S[mt][0][0], S[mt][0][1]);
                __half2 h1 = __floats2half2_rn(S[mt][0][2], S[mt][0][3]);
                __half2 h2 = __floats2half2_rn(S[mt][1][0], S[mt][1][1]);
                __half2 h3 = __floats2half2_rn(S[mt][1][2], S[mt][1][3]);
                pa[mt][0] = *reinterpret_cast<unsigned*>(&h0);
                pa[mt][1] = *reinterpret_cast<unsigned*>(&h1);
                pa[mt][2] = *reinterpret_cast<unsigned*>(&h2);
                pa[mt][3] = *reinterpret_cast<unsigned*>(&h3);
            }

            #pragma unroll
            for (int nd = 0; nd < 4; ++nd) {
                unsigned vb[2];
                unsigned addr = smem_u32(&Vt[nd*8 + vrow][kk*16 + vcol8]);
                LDSM_X2(vb[0], vb[1], addr);
                MMA_F16(O[0][nd], pa[0], vb[0], vb[1]);
                MMA_F16(O[1][nd], pa[1], vb[0], vb[1]);
            }
        }
    }

    if (finalWrite) {
        #pragma unroll
        for (int mt = 0; mt < 2; ++mt) {
            #pragma unroll
            for (int hf = 0; hf < 2; ++hf) {
                float inv = 1.0f / lrow[mt][hf];
                int r = b*QPER + w*32 + mt*16 + g + hf*8;
                #pragma unroll
                for (int nd = 0; nd < 4; ++nd) {
                    __half2 o = __floats2half2_rn(O[mt][nd][hf*2]*inv, O[mt][nd][hf*2+1]*inv);
                    *reinterpret_cast<__half2*>(&g_attn16[(size_t)r*CDIM + h*DH + nd*8 + 2*t]) = o;
                }
            }
        }
    } else {
        int base = (split*64 + bh)*QPER;
        #pragma unroll
        for (int mt = 0; mt < 2; ++mt) {
            #pragma unroll
            for (int hf = 0; hf < 2; ++hf) {
                int r = w*32 + mt*16 + g + hf*8;
                if (t == 0) {
                    g_pm[base + r] = mrow[mt][hf];
                    g_pl[base + r] = lrow[mt][hf];
                }
                #pragma unroll
                for (int nd = 0; nd < 4; ++nd) {
                    __half2 o = __floats2half2_rn(O[mt][nd][hf*2], O[mt][nd][hf*2+1]);
                    *reinterpret_cast<__half2*>(&g_po16[(size_t)(base + r)*DH + nd*8 + 2*t]) = o;
                }
            }
        }
    }
}

// ---------------- split-KV combine (writes f16 attn) ------------------------
__global__ void cross_attn_combine()
{
    int qi = blockIdx.x;
    int c = threadIdx.x;
    int h = c >> 5, d = c & 31;
    int b = qi >> 7, i = qi & 127;
    int bh = b*8 + h;
    float mv[NSPLIT], lv[NSPLIT];
    float Mx = -1e30f;
    #pragma unroll
    for (int s = 0; s < NSPLIT; ++s) {
        int base = (s*64 + bh)*QPER + i;
        mv[s] = g_pm[base];
        lv[s] = g_pl[base];
        Mx = fmaxf(Mx, mv[s]);
    }
    float O = 0.f, L = 0.f;
    #pragma unroll
    for (int s = 0; s < NSPLIT; ++s) {
        float wgt = fexp(mv[s] - Mx);
        int base = (s*64 + bh)*QPER + i;
        O = fmaf(wgt, __half2float(g_po16[(size_t)base*DH + d]), O);
        L = fmaf(wgt, lv[s], L);
    }
    g_attn16[(size_t)qi*CDIM + c] = __float2half(O / L);
}

// ---------------- launch ----------------------------------------------------
static inline void* symv(const void* symbol)
{
    void* p = nullptr;
    cudaGetSymbolAddress(&p, symbol);
    return p;
}

static inline Job mkjob_t(const __half* A, const __half* B, const float* bias,
                          const float* res, const float* rowS, const float* rowSS,
                          float* ssOut, const float* colS,
                          float* C, __half* C16, int M, int N, int K,
                          float scale, int mode, int BM, int BN)
{
    Job j;
    j.A = A; j.B = B; j.bias = bias; j.res = res; j.rowS = rowS; j.rowSS = rowSS;
    j.ssOut = ssOut; j.colS = colS;
    j.C = C; j.C16 = C16; j.N = N; j.K = K; j.nblocks = N/BN; j.nb_total = (M/BM)*(N/BN);
    j.mode = mode; j.scale = scale;
    return j;
}
#define mkjob_sm(...)  mkjob_t(__VA_ARGS__, 32, 64)
#define mkjob_big(...) mkjob_t(__VA_ARGS__, 64, 128)

static inline void run_sm(JobPack& P)
{
    int total = 0;
    for (int i = 0; i < P.njobs; ++i) total += P.jobs[i].nb_total;
    gemm_sm<<<total, 128>>>(P);
}
static inline void run_big(JobPack& P)
{
    int total = 0;
    for (int i = 0; i < P.njobs; ++i) total += P.jobs[i].nb_total;
    gemm_big<<<total, 256>>>(P);
}

extern "C" void kernel_launch(void* const* d_in, const int* in_sizes, int n_in,
                              void* d_out, int out_size)
{
    const float* q        = (const float*)d_in[0];
    const float* kv       = (const float*)d_in[1];
    const float* w_norm_kv= (const float*)d_in[4];
    const float* w_norm1  = (const float*)d_in[5];
    const float* w_norm2  = (const float*)d_in[6];
    const float* w_norm3  = (const float*)d_in[7];
    const float* wq_c     = (const float*)d_in[8];
    const float* wk_c     = (const float*)d_in[9];
    const float* wv_c     = (const float*)d_in[10];
    const float* wo_c     = (const float*)d_in[11];
    const float* bo_c     = (const float*)d_in[12];
    const float* wq_s     = (const float*)d_in[13];
    const float* wkv_s    = (const float*)d_in[14];
    const float* wo_s     = (const float*)d_in[15];
    const float* bo_s     = (const float*)d_in[16];
    const float* w1_mlp   = (const float*)d_in[17];
    const float* b1_mlp   = (const float*)d_in[18];
    const float* w2_mlp   = (const float*)d_in[19];
    const float* b2_mlp   = (const float*)d_in[20];
    const float* w1_mask  = (const float*)d_in[21];
    const float* b1_mask  = (const float*)d_in[22];
    const float* w2_mask  = (const float*)d_in[23];
    const float* b2_mask  = (const float*)d_in[24];
    float* out = (float*)d_out;

    __half* p_Kc16 = (__half*)symv(g_Kc16);
    __half* p_Vc16 = (__half*)symv(g_Vc16);
    __half* p_mh16 = (__half*)symv(g_mh16);
    __half* p_mk16 = (__half*)symv(g_mk16);
    __half* p_z16  = (__half*)symv(g_z16);
    __half* p_Qc16 = (__half*)symv(g_Qc16);
    __half* p_at16 = (__half*)symv(g_attn16);
    float*  p_q1   = (float*) symv(g_q1);
    __half* p_q116 = (__half*)symv(g_q116);
    float*  p_q2   = (float*) symv(g_q2);
    __half* p_q216 = (__half*)symv(g_q216);
    __half* p_Qs16 = (__half*)symv(g_Qs16);
    __half* p_KVs16= (__half*)symv(g_KVs16);
    __half* p_hid16= (__half*)symv(g_hid16);
    __half* p_wqc  = (__half*)symv(g_wqc16);
    __half* p_wkc  = (__half*)symv(g_wkc16);
    __half* p_wvc  = (__half*)symv(g_wvc16);
    __half* p_wqs  = (__half*)symv(g_wqs16);
    __half* p_wkvs = (__half*)symv(g_wkvs16);
    __half* p_w1   = (__half*)symv(g_w116);
    __half* p_w1m  = (__half*)symv(g_w1m16);
    __half* p_w2m  = (__half*)symv(g_w2m16);
    __half* p_woc  = (__half*)symv(g_woc16);
    __half* p_wos  = (__half*)symv(g_wos16);
    __half* p_w2   = (__half*)symv(g_w216);
    __half* p_q16  = (__half*)symv(g_q16);
    __half* p_kv16 = (__half*)symv(g_kv16);
    float*  p_skv  = (float*) symv(g_skv);
    float*  p_sq   = (float*) symv(g_sq);
    float*  p_ssq1 = (float*) symv(g_ssq1);
    float*  p_ssq2 = (float*) symv(g_ssq2);

    // L1: vectorized convert + row scales + zero ssq
    prep<<<PREP_A + PREP_B + PREP_C, 256>>>(
        wq_c, wk_c, wv_c, wq_s, wkv_s, w1_mlp,
        w1_mask, w2_mask, wo_c, wo_s, w2_mlp,
        w_norm1, w_norm_kv, w_norm2, w_norm3, kv, q);
    // L2: mh = gelu(q @ w1m^T + b1)
    {
        JobPack P; P.njobs = 1;
        P.jobs[0] = mkjob_sm(p_q16, p_w1m, b1_mask, nullptr, nullptr, nullptr, nullptr, nullptr,
                             nullptr, p_mh16, NQ, CDIM, CDIM, 1.f, 1);
        run_sm(P);
    }
    // L3: mk = (mh @ w2m^T + b2) ∘ w_norm_kv
    {
        JobPack P; P.njobs = 1;
        P.jobs[0] = mkjob_sm(p_mh16, p_w2m, b2_mask, nullptr, nullptr, nullptr, nullptr, w_norm_kv,
                             nullptr, p_mk16, NQ, CDIM, CDIM, 1.f, 0);
        run_sm(P);
    }
    // L4: BIG — Kc, Vc, Qc, zT(8 batches) in one launch (64x128 tiles)
    {
        JobPack P; P.njobs = 11;
        P.jobs[0] = mkjob_big(p_kv16, p_wkc, nullptr, nullptr, p_skv, nullptr, nullptr, nullptr,
                              nullptr, p_Kc16, NKV, CDIM, CDIM, 1.f, 0);
        P.jobs[1] = mkjob_big(p_kv16, p_wvc, nullptr, nullptr, p_skv, nullptr, nullptr, nullptr,
                              nullptr, p_Vc16, NKV, CDIM, CDIM, 1.f, 0);
        P.jobs[2] = mkjob_big(p_q16, p_wqc, nullptr, nullptr, p_sq, nullptr, nullptr, nullptr,
                              nullptr, p_Qc16, NQ, CDIM, CDIM, ATTN_SCALE, 0);
        for (int b = 0; b < BATCH; ++b)
            P.jobs[3+b] = mkjob_big(p_mk16 + (size_t)b*QPER*CDIM, p_kv16 + (size_t)b*KVPER*CDIM,
                                    nullptr, nullptr, nullptr, nullptr, nullptr, p_skv + b*KVPER,
                                    nullptr, p_z16 + (size_t)b*QPER*KVPER, QPER, KVPER, CDIM, 1.f, 2);
        run_big(P);
    }
    // L5: cross attention (split-KV partials, all-f16 operands)
    attn_mma<<<dim3(64, NSPLIT), 128>>>(p_Qc16, p_Kc16, p_Vc16, CDIM, KVPER,
                                        p_z16, KVPER, KVPER/NSPLIT, 0);
    // L6: combine -> attn16
    cross_attn_combine<<<NQ, CDIM>>>();
    // L7: q1 = q + attn @ wo_c^T + bo_c  (+ssq1, f16 shadow)
    {
        JobPack P; P.njobs = 1;
        P.jobs[0] = mkjob_sm(p_at16, p_woc, bo_c, q, nullptr, nullptr, p_ssq1, nullptr,
                             p_q1, p_q116, NQ, CDIM, CDIM, 1.f, 0);
        run_sm(P);
    }
    // L8: Qs + KVs (rms via ssq1, f16 out)
    {
        JobPack P; P.njobs = 2;
        P.jobs[0] = mkjob_sm(p_q116, p_wqs, nullptr, nullptr, nullptr, p_ssq1, nullptr, nullptr,
                             nullptr, p_Qs16, NQ, CDIM, CDIM, ATTN_SCALE, 0);
        P.jobs[1] = mkjob_sm(p_q116, p_wkvs, nullptr, nullptr, nullptr, p_ssq1, nullptr, nullptr,
                             nullptr, p_KVs16, NQ, 2*CDIM, CDIM, 1.f, 0);
        run_sm(P);
    }
    // L9: self attention (direct f16 write)
    attn_mma<<<dim3(64, 1), 128>>>(p_Qs16, p_KVs16, p_KVs16 + CDIM, 2*CDIM, QPER,
                                   nullptr, 0, QPER, 1);
    // L10: q2 = q1 + attn @ wo_s^T + bo_s  (+ssq2, f16 shadow)
    {
        JobPack P; P.njobs = 1;
        P.jobs[0] = mkjob_sm(p_at16, p_wos, bo_s, p_q1, nullptr, nullptr, p_ssq2, nullptr,
                             p_q2, p_q216, NQ, CDIM, CDIM, 1.f, 0);
        run_sm(P);
    }
    // L11: hid = gelu(rms(q2) @ w1'^T + b1)  (f16 only)
    {
        JobPack P; P.njobs = 1;
        P.jobs[0] = mkjob_sm(p_q216, p_w1, b1_mlp, nullptr, nullptr, p_ssq2, nullptr, nullptr,
                             nullptr, p_hid16, NQ, 4*CDIM, CDIM, 1.f, 1);
        run_sm(P);
    }
    // L12: out = q2 + hid @ w2^T + b2
    {
        JobPack P; P.njobs = 1;
        P.jobs[0] = mkjob_sm(p_hid16, p_w2, b2_mlp, p_q2, nullptr, nullptr, nullptr, nullptr,
                             out, nullptr, NQ, CDIM, 4*CDIM, 1.f, 0);
        run_sm(P);
    }
}